// round 1
// baseline (speedup 1.0000x reference)
#include <cuda_runtime.h>
#include <math.h>

// Problem constants (fixed shapes)
#define SRC_LEN 512
#define BSZ     16
#define SNT_LEN 512
#define E_DIM   512
#define C_DIM   512
#define V_DIM   12000
#define EXT_DIM 500
#define TOT_DIM (V_DIM + EXT_DIM)       // 12500
#define M_ROWS  (SRC_LEN * BSZ)         // 8192
#define LL_ELEMS ((size_t)M_ROWS * TOT_DIM)

// Scratch (device globals — no allocations allowed)
__device__ float g_h[(size_t)M_ROWS * C_DIM];     // tanh(concept @ Wt^T + bt)
__device__ float g_gates[M_ROWS * 3];             // per row: gen, copy, map

// ---------------------------------------------------------------------------
// Classic fp32 SGEMM, C[m,n] = act( sum_k A[m,k]*B[n,k] + bias[n] )
// A: MxK row-major, B: NxK row-major (both K-contiguous -> "NT" gemm)
// BM=BN=128, BK=8, 256 threads, 8x8 per-thread tile.
// ---------------------------------------------------------------------------
template <int ACT_TANH>
__global__ __launch_bounds__(256) void sgemm_nt_kernel(
    const float* __restrict__ A, const float* __restrict__ B,
    const float* __restrict__ bias, float* __restrict__ C,
    int M, int N, int K, int ldc)
{
    __shared__ float As[8][128];
    __shared__ float Bs[8][128];

    const int tid = threadIdx.x;
    const int m0 = blockIdx.y * 128;
    const int n0 = blockIdx.x * 128;
    const int tx = tid & 15;       // 0..15
    const int ty = tid >> 4;       // 0..15

    float acc[8][8];
#pragma unroll
    for (int i = 0; i < 8; i++)
#pragma unroll
        for (int j = 0; j < 8; j++) acc[i][j] = 0.f;

    const int lrow = tid >> 1;          // 0..127
    const int lcol = (tid & 1) * 4;     // 0 or 4
    const float* Aptr = A + (size_t)(m0 + lrow) * K + lcol;
    const bool bvalid = (n0 + lrow) < N;
    const float* Bptr = B + (size_t)(n0 + lrow) * K + lcol;

    for (int k0 = 0; k0 < K; k0 += 8) {
        float4 av = *reinterpret_cast<const float4*>(Aptr + k0);
        float4 bv = make_float4(0.f, 0.f, 0.f, 0.f);
        if (bvalid) bv = *reinterpret_cast<const float4*>(Bptr + k0);

        As[lcol + 0][lrow] = av.x;
        As[lcol + 1][lrow] = av.y;
        As[lcol + 2][lrow] = av.z;
        As[lcol + 3][lrow] = av.w;
        Bs[lcol + 0][lrow] = bv.x;
        Bs[lcol + 1][lrow] = bv.y;
        Bs[lcol + 2][lrow] = bv.z;
        Bs[lcol + 3][lrow] = bv.w;
        __syncthreads();

#pragma unroll
        for (int kk = 0; kk < 8; kk++) {
            float4 a0 = *reinterpret_cast<const float4*>(&As[kk][ty * 8]);
            float4 a1 = *reinterpret_cast<const float4*>(&As[kk][ty * 8 + 4]);
            float4 b0 = *reinterpret_cast<const float4*>(&Bs[kk][tx * 8]);
            float4 b1 = *reinterpret_cast<const float4*>(&Bs[kk][tx * 8 + 4]);
            float a[8] = {a0.x, a0.y, a0.z, a0.w, a1.x, a1.y, a1.z, a1.w};
            float b[8] = {b0.x, b0.y, b0.z, b0.w, b1.x, b1.y, b1.z, b1.w};
#pragma unroll
            for (int i = 0; i < 8; i++)
#pragma unroll
                for (int j = 0; j < 8; j++)
                    acc[i][j] = fmaf(a[i], b[j], acc[i][j]);
        }
        __syncthreads();
    }

#pragma unroll
    for (int i = 0; i < 8; i++) {
        const int m = m0 + ty * 8 + i;
#pragma unroll
        for (int j = 0; j < 8; j++) {
            const int n = n0 + tx * 8 + j;
            if (n < N) {
                float v = acc[i][j] + bias[n];
                if (ACT_TANH) v = tanhf(v);
                C[(size_t)m * ldc + n] = v;
            }
        }
    }
}

// ---------------------------------------------------------------------------
// gates: per row r, u_j = h_row . W_div[j] + b_div[j]; softmax over 3.
// Store gen (=g0), copy (=g2), map (=g1). One warp per row.
// ---------------------------------------------------------------------------
__global__ __launch_bounds__(256) void gates_kernel(
    const float* __restrict__ Wdiv, const float* __restrict__ bdiv)
{
    const int warp = (blockIdx.x * blockDim.x + threadIdx.x) >> 5;
    const int lane = threadIdx.x & 31;
    if (warp >= M_ROWS) return;
    const float* hrow = g_h + (size_t)warp * C_DIM;
    float s0 = 0.f, s1 = 0.f, s2 = 0.f;
    for (int k = lane; k < C_DIM; k += 32) {
        float hv = hrow[k];
        s0 = fmaf(hv, Wdiv[0 * C_DIM + k], s0);
        s1 = fmaf(hv, Wdiv[1 * C_DIM + k], s1);
        s2 = fmaf(hv, Wdiv[2 * C_DIM + k], s2);
    }
#pragma unroll
    for (int o = 16; o > 0; o >>= 1) {
        s0 += __shfl_xor_sync(0xffffffffu, s0, o);
        s1 += __shfl_xor_sync(0xffffffffu, s1, o);
        s2 += __shfl_xor_sync(0xffffffffu, s2, o);
    }
    if (lane == 0) {
        s0 += bdiv[0]; s1 += bdiv[1]; s2 += bdiv[2];
        float mx = fmaxf(s0, fmaxf(s1, s2));
        float e0 = expf(s0 - mx), e1 = expf(s1 - mx), e2 = expf(s2 - mx);
        float inv = 1.f / (e0 + e1 + e2);
        g_gates[warp * 3 + 0] = e0 * inv;  // gen
        g_gates[warp * 3 + 1] = e2 * inv;  // copy (gates[...,2])
        g_gates[warp * 3 + 2] = e1 * inv;  // map  (gates[...,1])
    }
}

// ---------------------------------------------------------------------------
// Per-row: softmax(logits)*gen, zero-extend to 12500, scatter-add copy probs,
// log(p + 1e-12). One block (512 thr) per row, whole row in shared (50 KB).
// logits are read from (and ll written to) the same region of d_out.
// ---------------------------------------------------------------------------
__global__ __launch_bounds__(512) void softmax_scatter_log_kernel(
    float* __restrict__ out,
    const float* __restrict__ align,        // (SRC, B, SNT)
    const int*   __restrict__ copy_seq)     // (SNT, B, 2)
{
    extern __shared__ float buf[];          // TOT_DIM floats
    __shared__ float red[17];

    const int r = blockIdx.x;               // r = s*B + b
    const int s = r / BSZ;
    const int b = r % BSZ;
    const int tid = threadIdx.x;
    float* row = out + (size_t)r * TOT_DIM;

    // pass 1: load logits, find max
    float lmax = -3.0e38f;
    for (int c = tid; c < V_DIM; c += 512) {
        float v = row[c];
        buf[c] = v;
        lmax = fmaxf(lmax, v);
    }
#pragma unroll
    for (int o = 16; o > 0; o >>= 1)
        lmax = fmaxf(lmax, __shfl_xor_sync(0xffffffffu, lmax, o));
    if ((tid & 31) == 0) red[tid >> 5] = lmax;
    __syncthreads();
    if (tid < 32) {
        float v = (tid < 16) ? red[tid] : -3.0e38f;
#pragma unroll
        for (int o = 8; o > 0; o >>= 1)
            v = fmaxf(v, __shfl_xor_sync(0xffffffffu, v, o));
        if (tid == 0) red[16] = v;
    }
    __syncthreads();
    const float mx = red[16];

    // pass 2: exp + sum; zero-extend ext columns
    float lsum = 0.f;
    for (int c = tid; c < V_DIM; c += 512) {
        float e = expf(buf[c] - mx);
        buf[c] = e;
        lsum += e;
    }
    for (int c = V_DIM + tid; c < TOT_DIM; c += 512) buf[c] = 0.f;
    __syncthreads();   // protect red[] reuse
#pragma unroll
    for (int o = 16; o > 0; o >>= 1)
        lsum += __shfl_xor_sync(0xffffffffu, lsum, o);
    if ((tid & 31) == 0) red[tid >> 5] = lsum;
    __syncthreads();
    if (tid < 32) {
        float v = (tid < 16) ? red[tid] : 0.f;
#pragma unroll
        for (int o = 8; o > 0; o >>= 1)
            v += __shfl_xor_sync(0xffffffffu, v, o);
        if (tid == 0) red[16] = v;
    }
    __syncthreads();
    const float sum = red[16];

    const float gen = g_gates[r * 3 + 0];
    const float cpy = g_gates[r * 3 + 1];
    const float mp  = g_gates[r * 3 + 2];
    const float scale = gen / sum;

    for (int c = tid; c < V_DIM; c += 512) buf[c] *= scale;
    __syncthreads();

    // scatter-add 1024 copy probabilities (j = snt*2 + k)
    const float* arow = align + ((size_t)s * BSZ + b) * SNT_LEN;
    for (int j = tid; j < 2 * SNT_LEN; j += 512) {
        int snt = j >> 1;
        int k = j & 1;
        int idx = copy_seq[((size_t)snt * BSZ + b) * 2 + k];
        float v = (k == 0 ? cpy : mp) * arow[snt];
        if (idx >= 0 && idx < TOT_DIM) atomicAdd(&buf[idx], v);
    }
    __syncthreads();

    // write log(p + 1e-12)
    for (int c = tid; c < TOT_DIM; c += 512)
        row[c] = logf(buf[c] + 1e-12f);
}

// ---------------------------------------------------------------------------
// arc_ll = log(arc + 1e-12), float4-vectorized
// ---------------------------------------------------------------------------
__global__ __launch_bounds__(256) void arc_log_kernel(
    const float4* __restrict__ in, float4* __restrict__ out, int n4)
{
    int i = blockIdx.x * blockDim.x + threadIdx.x;
    if (i < n4) {
        float4 v = in[i];
        v.x = logf(v.x + 1e-12f);
        v.y = logf(v.y + 1e-12f);
        v.z = logf(v.z + 1e-12f);
        v.w = logf(v.w + 1e-12f);
        out[i] = v;
    }
}

// ---------------------------------------------------------------------------
extern "C" void kernel_launch(void* const* d_in, const int* in_sizes, int n_in,
                              void* d_out, int out_size)
{
    const float* align    = (const float*)d_in[0];   // alignment_weight (SRC,B,SNT)
    const float* arc      = (const float*)d_in[1];   // arc_weight (SRC,B,SRC)
    const float* concept  = (const float*)d_in[3];   // concept_outs (SRC,B,E)
    const int*   copy_seq = (const int*)  d_in[4];   // (SNT,B,2)
    const float* Wt       = (const float*)d_in[9];   // W_transfer (C,E)
    const float* bt       = (const float*)d_in[10];  // b_transfer (C,)
    const float* Wg       = (const float*)d_in[11];  // W_gen (V,C)
    const float* bg       = (const float*)d_in[12];  // b_gen (V,)
    const float* Wd       = (const float*)d_in[13];  // W_div (3,C)
    const float* bd       = (const float*)d_in[14];  // b_div (3,)

    float* out = (float*)d_out;
    float* ll = out;                         // (SRC,B,TOT)
    float* arc_ll = out + LL_ELEMS;          // (SRC,B,SRC)

    float* hptr = nullptr;
    cudaGetSymbolAddress((void**)&hptr, g_h);

    // 1) h = tanh(concept @ Wt^T + bt)   [8192 x 512]
    {
        dim3 grid(C_DIM / 128, M_ROWS / 128);
        sgemm_nt_kernel<1><<<grid, 256>>>(concept, Wt, bt, hptr,
                                          M_ROWS, C_DIM, E_DIM, C_DIM);
    }

    // 2) gates
    gates_kernel<<<(M_ROWS * 32) / 256, 256>>>(Wd, bd);

    // 3) logits = h @ Wg^T + bg  -> staged into ll region (cols 0..11999)
    {
        dim3 grid((V_DIM + 127) / 128, M_ROWS / 128);
        sgemm_nt_kernel<0><<<grid, 256>>>(hptr, Wg, bg, ll,
                                          M_ROWS, V_DIM, C_DIM, TOT_DIM);
    }

    // 4) softmax * gen, zero-extend, scatter copy probs, log
    {
        int smem = TOT_DIM * sizeof(float);  // 50000 B
        cudaFuncSetAttribute(softmax_scatter_log_kernel,
                             cudaFuncAttributeMaxDynamicSharedMemorySize, smem);
        softmax_scatter_log_kernel<<<M_ROWS, 512, smem>>>(ll, align, copy_seq);
    }

    // 5) arc_ll
    {
        int n4 = (SRC_LEN * BSZ * SRC_LEN) / 4;
        arc_log_kernel<<<(n4 + 255) / 256, 256>>>((const float4*)arc,
                                                  (float4*)arc_ll, n4);
    }
}

// round 3
// speedup vs baseline: 4.0392x; 4.0392x over previous
#include <cuda_runtime.h>
#include <cuda_bf16.h>
#include <math.h>
#include <stdint.h>

// Problem constants (fixed shapes)
#define SRC_LEN 512
#define BSZ     16
#define SNT_LEN 512
#define E_DIM   512
#define C_DIM   512
#define V_DIM   12000
#define EXT_DIM 500
#define TOT_DIM (V_DIM + EXT_DIM)       // 12500
#define M_ROWS  (SRC_LEN * BSZ)         // 8192
#define LL_ELEMS ((size_t)M_ROWS * TOT_DIM)

// Scratch (device globals — no allocations allowed)
__device__ float g_h[(size_t)M_ROWS * C_DIM];            // fp32 h (for gates)
__device__ __nv_bfloat16 g_h_bf[(size_t)M_ROWS * C_DIM]; // bf16 h (for GEMM2)
__device__ __nv_bfloat16 g_Wg_bf[(size_t)V_DIM * C_DIM]; // bf16 W_gen
__device__ float g_gates[M_ROWS * 3];                    // per row: gen, copy, map

// ===========================================================================
// bf16 mma.sync GEMM2: C[m,n] = sum_k A[m,k]*B[n,k] + bias[n]
// A: [8192,512] bf16 row-major, B: [12000,512] bf16 row-major, C fp32 ld=12500
// CTA 128x128, BK=64, 256 thr, 8 warps (2m x 4n), warp tile 64x32.
// cp.async double buffer; ldmatrix.x4; mma.m16n8k16.
// ===========================================================================
#define GK   512
#define BK   64
#define NKT  (GK / BK)            // 8
#define ROWB 144                  // padded smem row stride (bytes) for 128B of k
#define STAGE_BYTES (128 * ROWB)  // 18432 per operand
#define GEMM2_SMEM  (2 * 2 * STAGE_BYTES)  // 73728

__device__ __forceinline__ uint32_t smem_u32(const void* p) {
    uint32_t a;
    asm("{ .reg .u64 t; cvta.to.shared.u64 t, %1; cvt.u32.u64 %0, t; }"
        : "=r"(a) : "l"(p));
    return a;
}

__device__ __forceinline__ void cp16(uint32_t saddr, const void* gaddr, uint32_t srcsz) {
    asm volatile("cp.async.cg.shared.global [%0], [%1], 16, %2;"
                 :: "r"(saddr), "l"(gaddr), "r"(srcsz));
}
__device__ __forceinline__ void cp_commit() {
    asm volatile("cp.async.commit_group;");
}
template <int N>
__device__ __forceinline__ void cp_wait() {
    asm volatile("cp.async.wait_group %0;" :: "n"(N));
}
__device__ __forceinline__ void ldmx4(uint32_t addr, uint32_t& r0, uint32_t& r1,
                                      uint32_t& r2, uint32_t& r3) {
    asm volatile("ldmatrix.sync.aligned.m8n8.x4.shared.b16 {%0,%1,%2,%3}, [%4];"
                 : "=r"(r0), "=r"(r1), "=r"(r2), "=r"(r3) : "r"(addr));
}
__device__ __forceinline__ void mma16816(float& c0, float& c1, float& c2, float& c3,
                                         uint32_t a0, uint32_t a1, uint32_t a2, uint32_t a3,
                                         uint32_t b0, uint32_t b1) {
    asm volatile(
        "mma.sync.aligned.m16n8k16.row.col.f32.bf16.bf16.f32 "
        "{%0,%1,%2,%3}, {%4,%5,%6,%7}, {%8,%9}, {%0,%1,%2,%3};"
        : "+f"(c0), "+f"(c1), "+f"(c2), "+f"(c3)
        : "r"(a0), "r"(a1), "r"(a2), "r"(a3), "r"(b0), "r"(b1));
}

__global__ __launch_bounds__(256) void gemm2_mma_kernel(
    const __nv_bfloat16* __restrict__ A,
    const __nv_bfloat16* __restrict__ B,
    const float* __restrict__ bias,
    float* __restrict__ C)
{
    extern __shared__ char smem[];
    const uint32_t sbase = smem_u32(smem);
    const int tid  = threadIdx.x;
    const int wid  = tid >> 5;
    const int lane = tid & 31;
    const int m0 = blockIdx.y * 128;
    const int n0 = blockIdx.x * 128;
    const int warp_m = wid & 1;       // 0..1
    const int warp_n = wid >> 1;      // 0..3

    // stage s: A at s*2*STAGE_BYTES, B at s*2*STAGE_BYTES + STAGE_BYTES
    auto a_off = [&](int s) -> uint32_t { return sbase + s * 2 * STAGE_BYTES; };
    auto b_off = [&](int s) -> uint32_t { return sbase + s * 2 * STAGE_BYTES + STAGE_BYTES; };

    // global load mapping: 1024 16B-chunks per operand per stage; 4 per thread
    // idx = tid + u*256; row = idx>>3; c = idx&7
    auto issue_stage = [&](int kt, int s) {
        const int k0 = kt * BK;
#pragma unroll
        for (int u = 0; u < 4; u++) {
            int idx = tid + u * 256;
            int row = idx >> 3;
            int c   = idx & 7;
            uint32_t sa = a_off(s) + row * ROWB + c * 16;
            const void* ga = A + (size_t)(m0 + row) * GK + k0 + c * 8;
            cp16(sa, ga, 16);
        }
#pragma unroll
        for (int u = 0; u < 4; u++) {
            int idx = tid + u * 256;
            int row = idx >> 3;
            int c   = idx & 7;
            uint32_t sa = b_off(s) + row * ROWB + c * 16;
            int gr = n0 + row;
            const void* ga = B + (size_t)(gr < V_DIM ? gr : V_DIM - 1) * GK + k0 + c * 8;
            cp16(sa, ga, (gr < V_DIM) ? 16u : 0u);   // zero-fill OOB rows
        }
        cp_commit();
    };

    float acc[4][4][4];
#pragma unroll
    for (int i = 0; i < 4; i++)
#pragma unroll
        for (int j = 0; j < 4; j++)
#pragma unroll
            for (int e = 0; e < 4; e++) acc[i][j][e] = 0.f;

    issue_stage(0, 0);

    const int g    = lane >> 3;     // 0..3
    const int lrow = lane & 7;      // 0..7

    for (int kt = 0; kt < NKT; kt++) {
        const int s = kt & 1;
        if (kt + 1 < NKT) {
            issue_stage(kt + 1, (kt + 1) & 1);
            cp_wait<1>();
        } else {
            cp_wait<0>();
        }
        __syncthreads();

        const uint32_t abase = a_off(s);
        const uint32_t bbase = b_off(s);

#pragma unroll
        for (int ks = 0; ks < 4; ks++) {          // 4 k16 steps in BK=64
            // A fragments: 4 m16 tiles
            uint32_t a[4][4];
#pragma unroll
            for (int mt = 0; mt < 4; mt++) {
                int row = warp_m * 64 + mt * 16 + lrow + (g & 1) * 8;
                int chunk = ks * 2 + (g >> 1);
                ldmx4(abase + row * ROWB + chunk * 16,
                      a[mt][0], a[mt][1], a[mt][2], a[mt][3]);
            }
            // B fragments: 2 ldmatrix covering 32 n (4 n8 tiles)
            uint32_t b[4][2];
#pragma unroll
            for (int nt = 0; nt < 2; nt++) {
                int row = warp_n * 32 + nt * 16 + lrow + (g >> 1) * 8;
                int chunk = ks * 2 + (g & 1);
                uint32_t r0, r1, r2, r3;
                ldmx4(bbase + row * ROWB + chunk * 16, r0, r1, r2, r3);
                b[nt * 2 + 0][0] = r0; b[nt * 2 + 0][1] = r1;
                b[nt * 2 + 1][0] = r2; b[nt * 2 + 1][1] = r3;
            }
#pragma unroll
            for (int mt = 0; mt < 4; mt++)
#pragma unroll
                for (int nt = 0; nt < 4; nt++)
                    mma16816(acc[mt][nt][0], acc[mt][nt][1],
                             acc[mt][nt][2], acc[mt][nt][3],
                             a[mt][0], a[mt][1], a[mt][2], a[mt][3],
                             b[nt][0], b[nt][1]);
        }
        __syncthreads();
    }

    // ---- epilogue: direct stores with bias ----
    const int trow = lane >> 2;         // 0..7
    const int tcol = (lane & 3) * 2;    // 0,2,4,6
#pragma unroll
    for (int mt = 0; mt < 4; mt++) {
#pragma unroll
        for (int nt = 0; nt < 4; nt++) {
            int gm = m0 + warp_m * 64 + mt * 16 + trow;
            int gn = n0 + warp_n * 32 + nt * 8 + tcol;
            if (gn + 1 < V_DIM) {
                float2 bv = *reinterpret_cast<const float2*>(bias + gn);
                float2 v0 = make_float2(acc[mt][nt][0] + bv.x, acc[mt][nt][1] + bv.y);
                float2 v1 = make_float2(acc[mt][nt][2] + bv.x, acc[mt][nt][3] + bv.y);
                *reinterpret_cast<float2*>(C + (size_t)gm * TOT_DIM + gn) = v0;
                *reinterpret_cast<float2*>(C + (size_t)(gm + 8) * TOT_DIM + gn) = v1;
            } else if (gn < V_DIM) {
                float bb = bias[gn];
                C[(size_t)gm * TOT_DIM + gn] = acc[mt][nt][0] + bb;
                C[(size_t)(gm + 8) * TOT_DIM + gn] = acc[mt][nt][2] + bb;
            }
        }
    }
}

// ===========================================================================
// fp32 SGEMM for GEMM1 (h = tanh(concept @ Wt^T + bt))
// ===========================================================================
template <int ACT_TANH>
__global__ __launch_bounds__(256) void sgemm_nt_kernel(
    const float* __restrict__ A, const float* __restrict__ B,
    const float* __restrict__ bias, float* __restrict__ C,
    int M, int N, int K, int ldc)
{
    __shared__ float As[8][128];
    __shared__ float Bs[8][128];

    const int tid = threadIdx.x;
    const int m0 = blockIdx.y * 128;
    const int n0 = blockIdx.x * 128;
    const int tx = tid & 15;
    const int ty = tid >> 4;

    float acc[8][8];
#pragma unroll
    for (int i = 0; i < 8; i++)
#pragma unroll
        for (int j = 0; j < 8; j++) acc[i][j] = 0.f;

    const int lrow = tid >> 1;
    const int lcol = (tid & 1) * 4;
    const float* Aptr = A + (size_t)(m0 + lrow) * K + lcol;
    const bool bvalid = (n0 + lrow) < N;
    const float* Bptr = B + (size_t)(n0 + lrow) * K + lcol;

    for (int k0 = 0; k0 < K; k0 += 8) {
        float4 av = *reinterpret_cast<const float4*>(Aptr + k0);
        float4 bv = make_float4(0.f, 0.f, 0.f, 0.f);
        if (bvalid) bv = *reinterpret_cast<const float4*>(Bptr + k0);

        As[lcol + 0][lrow] = av.x;
        As[lcol + 1][lrow] = av.y;
        As[lcol + 2][lrow] = av.z;
        As[lcol + 3][lrow] = av.w;
        Bs[lcol + 0][lrow] = bv.x;
        Bs[lcol + 1][lrow] = bv.y;
        Bs[lcol + 2][lrow] = bv.z;
        Bs[lcol + 3][lrow] = bv.w;
        __syncthreads();

#pragma unroll
        for (int kk = 0; kk < 8; kk++) {
            float4 a0 = *reinterpret_cast<const float4*>(&As[kk][ty * 8]);
            float4 a1 = *reinterpret_cast<const float4*>(&As[kk][ty * 8 + 4]);
            float4 b0 = *reinterpret_cast<const float4*>(&Bs[kk][tx * 8]);
            float4 b1 = *reinterpret_cast<const float4*>(&Bs[kk][tx * 8 + 4]);
            float a[8] = {a0.x, a0.y, a0.z, a0.w, a1.x, a1.y, a1.z, a1.w};
            float b[8] = {b0.x, b0.y, b0.z, b0.w, b1.x, b1.y, b1.z, b1.w};
#pragma unroll
            for (int i = 0; i < 8; i++)
#pragma unroll
                for (int j = 0; j < 8; j++)
                    acc[i][j] = fmaf(a[i], b[j], acc[i][j]);
        }
        __syncthreads();
    }

#pragma unroll
    for (int i = 0; i < 8; i++) {
        const int m = m0 + ty * 8 + i;
#pragma unroll
        for (int j = 0; j < 8; j++) {
            const int n = n0 + tx * 8 + j;
            if (n < N) {
                float v = acc[i][j] + bias[n];
                if (ACT_TANH) v = tanhf(v);
                C[(size_t)m * ldc + n] = v;
            }
        }
    }
}

// ===========================================================================
// fp32 -> bf16 conversion (vectorized)
// ===========================================================================
__global__ __launch_bounds__(256) void f32_to_bf16_kernel(
    const float4* __restrict__ in, uint2* __restrict__ out, int n4)
{
    int i = blockIdx.x * blockDim.x + threadIdx.x;
    if (i < n4) {
        float4 v = in[i];
        __nv_bfloat162 lo = __floats2bfloat162_rn(v.x, v.y);
        __nv_bfloat162 hi = __floats2bfloat162_rn(v.z, v.w);
        uint2 o;
        o.x = *reinterpret_cast<uint32_t*>(&lo);
        o.y = *reinterpret_cast<uint32_t*>(&hi);
        out[i] = o;
    }
}

// ===========================================================================
// gates kernel
// ===========================================================================
__global__ __launch_bounds__(256) void gates_kernel(
    const float* __restrict__ Wdiv, const float* __restrict__ bdiv)
{
    const int warp = (blockIdx.x * blockDim.x + threadIdx.x) >> 5;
    const int lane = threadIdx.x & 31;
    if (warp >= M_ROWS) return;
    const float* hrow = g_h + (size_t)warp * C_DIM;
    float s0 = 0.f, s1 = 0.f, s2 = 0.f;
    for (int k = lane; k < C_DIM; k += 32) {
        float hv = hrow[k];
        s0 = fmaf(hv, Wdiv[0 * C_DIM + k], s0);
        s1 = fmaf(hv, Wdiv[1 * C_DIM + k], s1);
        s2 = fmaf(hv, Wdiv[2 * C_DIM + k], s2);
    }
#pragma unroll
    for (int o = 16; o > 0; o >>= 1) {
        s0 += __shfl_xor_sync(0xffffffffu, s0, o);
        s1 += __shfl_xor_sync(0xffffffffu, s1, o);
        s2 += __shfl_xor_sync(0xffffffffu, s2, o);
    }
    if (lane == 0) {
        s0 += bdiv[0]; s1 += bdiv[1]; s2 += bdiv[2];
        float mx = fmaxf(s0, fmaxf(s1, s2));
        float e0 = expf(s0 - mx), e1 = expf(s1 - mx), e2 = expf(s2 - mx);
        float inv = 1.f / (e0 + e1 + e2);
        g_gates[warp * 3 + 0] = e0 * inv;  // gen
        g_gates[warp * 3 + 1] = e2 * inv;  // copy (gates[...,2])
        g_gates[warp * 3 + 2] = e1 * inv;  // map  (gates[...,1])
    }
}

// ===========================================================================
// softmax + scatter + log
// ===========================================================================
__global__ __launch_bounds__(512) void softmax_scatter_log_kernel(
    float* __restrict__ out,
    const float* __restrict__ align,        // (SRC, B, SNT)
    const int*   __restrict__ copy_seq)     // (SNT, B, 2)
{
    extern __shared__ float buf[];          // TOT_DIM floats
    __shared__ float red[17];

    const int r = blockIdx.x;
    const int s = r / BSZ;
    const int b = r % BSZ;
    const int tid = threadIdx.x;
    float* row = out + (size_t)r * TOT_DIM;

    float lmax = -3.0e38f;
    for (int c = tid; c < V_DIM; c += 512) {
        float v = row[c];
        buf[c] = v;
        lmax = fmaxf(lmax, v);
    }
#pragma unroll
    for (int o = 16; o > 0; o >>= 1)
        lmax = fmaxf(lmax, __shfl_xor_sync(0xffffffffu, lmax, o));
    if ((tid & 31) == 0) red[tid >> 5] = lmax;
    __syncthreads();
    if (tid < 32) {
        float v = (tid < 16) ? red[tid] : -3.0e38f;
#pragma unroll
        for (int o = 8; o > 0; o >>= 1)
            v = fmaxf(v, __shfl_xor_sync(0xffffffffu, v, o));
        if (tid == 0) red[16] = v;
    }
    __syncthreads();
    const float mx = red[16];

    float lsum = 0.f;
    for (int c = tid; c < V_DIM; c += 512) {
        float e = expf(buf[c] - mx);
        buf[c] = e;
        lsum += e;
    }
    for (int c = V_DIM + tid; c < TOT_DIM; c += 512) buf[c] = 0.f;
    __syncthreads();
#pragma unroll
    for (int o = 16; o > 0; o >>= 1)
        lsum += __shfl_xor_sync(0xffffffffu, lsum, o);
    if ((tid & 31) == 0) red[tid >> 5] = lsum;
    __syncthreads();
    if (tid < 32) {
        float v = (tid < 16) ? red[tid] : 0.f;
#pragma unroll
        for (int o = 8; o > 0; o >>= 1)
            v += __shfl_xor_sync(0xffffffffu, v, o);
        if (tid == 0) red[16] = v;
    }
    __syncthreads();
    const float sum = red[16];

    const float gen = g_gates[r * 3 + 0];
    const float cpy = g_gates[r * 3 + 1];
    const float mp  = g_gates[r * 3 + 2];
    const float scale = gen / sum;

    for (int c = tid; c < V_DIM; c += 512) buf[c] *= scale;
    __syncthreads();

    const float* arow = align + ((size_t)s * BSZ + b) * SNT_LEN;
    for (int j = tid; j < 2 * SNT_LEN; j += 512) {
        int snt = j >> 1;
        int k = j & 1;
        int idx = copy_seq[((size_t)snt * BSZ + b) * 2 + k];
        float v = (k == 0 ? cpy : mp) * arow[snt];
        if (idx >= 0 && idx < TOT_DIM) atomicAdd(&buf[idx], v);
    }
    __syncthreads();

    for (int c = tid; c < TOT_DIM; c += 512)
        row[c] = logf(buf[c] + 1e-12f);
}

// ===========================================================================
// arc_ll = log(arc + 1e-12)
// ===========================================================================
__global__ __launch_bounds__(256) void arc_log_kernel(
    const float4* __restrict__ in, float4* __restrict__ out, int n4)
{
    int i = blockIdx.x * blockDim.x + threadIdx.x;
    if (i < n4) {
        float4 v = in[i];
        v.x = logf(v.x + 1e-12f);
        v.y = logf(v.y + 1e-12f);
        v.z = logf(v.z + 1e-12f);
        v.w = logf(v.w + 1e-12f);
        out[i] = v;
    }
}

// ===========================================================================
extern "C" void kernel_launch(void* const* d_in, const int* in_sizes, int n_in,
                              void* d_out, int out_size)
{
    const float* align    = (const float*)d_in[0];
    const float* arc      = (const float*)d_in[1];
    const float* concept  = (const float*)d_in[3];
    const int*   copy_seq = (const int*)  d_in[4];
    const float* Wt       = (const float*)d_in[9];
    const float* bt       = (const float*)d_in[10];
    const float* Wg       = (const float*)d_in[11];
    const float* bg       = (const float*)d_in[12];
    const float* Wd       = (const float*)d_in[13];
    const float* bd       = (const float*)d_in[14];

    float* out = (float*)d_out;
    float* ll = out;                         // (SRC,B,TOT)
    float* arc_ll = out + LL_ELEMS;          // (SRC,B,SRC)

    float* hptr = nullptr;
    cudaGetSymbolAddress((void**)&hptr, g_h);
    __nv_bfloat16* hbf = nullptr;
    cudaGetSymbolAddress((void**)&hbf, g_h_bf);
    __nv_bfloat16* wgbf = nullptr;
    cudaGetSymbolAddress((void**)&wgbf, g_Wg_bf);

    // 1) h = tanh(concept @ Wt^T + bt)   [8192 x 512] fp32
    {
        dim3 grid(C_DIM / 128, M_ROWS / 128);
        sgemm_nt_kernel<1><<<grid, 256>>>(concept, Wt, bt, hptr,
                                          M_ROWS, C_DIM, E_DIM, C_DIM);
    }

    // 2) conversions to bf16
    {
        int n4 = M_ROWS * C_DIM / 4;
        f32_to_bf16_kernel<<<(n4 + 255) / 256, 256>>>(
            (const float4*)hptr, (uint2*)hbf, n4);
        int n4w = V_DIM * C_DIM / 4;
        f32_to_bf16_kernel<<<(n4w + 255) / 256, 256>>>(
            (const float4*)Wg, (uint2*)wgbf, n4w);
    }

    // 3) gates (fp32 h)
    gates_kernel<<<(M_ROWS * 32) / 256, 256>>>(Wd, bd);

    // 4) logits = h @ Wg^T + bg via bf16 mma.sync -> staged into ll region
    {
        cudaFuncSetAttribute(gemm2_mma_kernel,
                             cudaFuncAttributeMaxDynamicSharedMemorySize,
                             GEMM2_SMEM);
        dim3 grid((V_DIM + 127) / 128, M_ROWS / 128);
        gemm2_mma_kernel<<<grid, 256, GEMM2_SMEM>>>(hbf, wgbf, bg, ll);
    }

    // 5) softmax * gen, zero-extend, scatter copy probs, log
    {
        int smem = TOT_DIM * sizeof(float);  // 50000 B
        cudaFuncSetAttribute(softmax_scatter_log_kernel,
                             cudaFuncAttributeMaxDynamicSharedMemorySize, smem);
        softmax_scatter_log_kernel<<<M_ROWS, 512, smem>>>(ll, align, copy_seq);
    }

    // 6) arc_ll
    {
        int n4 = (SRC_LEN * BSZ * SRC_LEN) / 4;
        arc_log_kernel<<<(n4 + 255) / 256, 256>>>((const float4*)arc,
                                                  (float4*)arc_ll, n4);
    }
}

// round 4
// speedup vs baseline: 4.8512x; 1.2010x over previous
#include <cuda_runtime.h>
#include <cuda_bf16.h>
#include <math.h>
#include <stdint.h>

// Problem constants (fixed shapes)
#define SRC_LEN 512
#define BSZ     16
#define SNT_LEN 512
#define E_DIM   512
#define C_DIM   512
#define V_DIM   12000
#define EXT_DIM 500
#define TOT_DIM (V_DIM + EXT_DIM)       // 12500
#define M_ROWS  (SRC_LEN * BSZ)         // 8192
#define LL_ELEMS ((size_t)M_ROWS * TOT_DIM)

// Scratch (device globals — no allocations allowed)
__device__ __nv_bfloat16 g_concept_bf[(size_t)M_ROWS * E_DIM];
__device__ __nv_bfloat16 g_Wt_bf[(size_t)C_DIM * E_DIM];
__device__ __nv_bfloat16 g_h_bf[(size_t)M_ROWS * C_DIM];
__device__ __nv_bfloat16 g_Wg_bf[(size_t)V_DIM * C_DIM];
__device__ float g_gates[M_ROWS * 3];   // per row: gen, copy, map

// ===========================================================================
// bf16 mma.sync GEMM (NT): C[m,n] = act( sum_k A[m,k]*B[n,k] + bias[n] )
// K fixed = 512. CTA 128x128, BK=64, 256 thr, 8 warps (2m x 4n), 3-stage
// cp.async pipeline, ldmatrix.x4, mma.m16n8k16.
// OUT_BF16=1: tanh + bf16 output.  OUT_BF16=0: fp32 output.
// ===========================================================================
#define GK   512
#define BK   64
#define NKT  (GK / BK)            // 8
#define ROWB 144                  // padded smem row stride (bytes)
#define STAGE_BYTES (128 * ROWB)  // 18432 per operand per stage
#define NSTAGE 3
#define GEMM_SMEM (NSTAGE * 2 * STAGE_BYTES)   // 110592

__device__ __forceinline__ uint32_t smem_u32(const void* p) {
    uint32_t a;
    asm("{ .reg .u64 t; cvta.to.shared.u64 t, %1; cvt.u32.u64 %0, t; }"
        : "=r"(a) : "l"(p));
    return a;
}
__device__ __forceinline__ void cp16(uint32_t saddr, const void* gaddr, uint32_t srcsz) {
    asm volatile("cp.async.cg.shared.global [%0], [%1], 16, %2;"
                 :: "r"(saddr), "l"(gaddr), "r"(srcsz));
}
__device__ __forceinline__ void cp_commit() {
    asm volatile("cp.async.commit_group;");
}
template <int N>
__device__ __forceinline__ void cp_wait() {
    asm volatile("cp.async.wait_group %0;" :: "n"(N));
}
__device__ __forceinline__ void ldmx4(uint32_t addr, uint32_t& r0, uint32_t& r1,
                                      uint32_t& r2, uint32_t& r3) {
    asm volatile("ldmatrix.sync.aligned.m8n8.x4.shared.b16 {%0,%1,%2,%3}, [%4];"
                 : "=r"(r0), "=r"(r1), "=r"(r2), "=r"(r3) : "r"(addr));
}
__device__ __forceinline__ void mma16816(float& c0, float& c1, float& c2, float& c3,
                                         uint32_t a0, uint32_t a1, uint32_t a2, uint32_t a3,
                                         uint32_t b0, uint32_t b1) {
    asm volatile(
        "mma.sync.aligned.m16n8k16.row.col.f32.bf16.bf16.f32 "
        "{%0,%1,%2,%3}, {%4,%5,%6,%7}, {%8,%9}, {%0,%1,%2,%3};"
        : "+f"(c0), "+f"(c1), "+f"(c2), "+f"(c3)
        : "r"(a0), "r"(a1), "r"(a2), "r"(a3), "r"(b0), "r"(b1));
}

template <int OUT_BF16>
__global__ __launch_bounds__(256) void gemm_mma_kernel(
    const __nv_bfloat16* __restrict__ A,
    const __nv_bfloat16* __restrict__ B,
    const float* __restrict__ bias,
    float* __restrict__ Cf,
    __nv_bfloat16* __restrict__ Cb,
    int N, int ldc)
{
    extern __shared__ char smem[];
    const uint32_t sbase = smem_u32(smem);
    const int tid  = threadIdx.x;
    const int wid  = tid >> 5;
    const int lane = tid & 31;
    const int m0 = blockIdx.y * 128;
    const int n0 = blockIdx.x * 128;
    const int warp_m = wid & 1;       // 0..1
    const int warp_n = wid >> 1;      // 0..3

    auto a_off = [&](int s) -> uint32_t { return sbase + s * 2 * STAGE_BYTES; };
    auto b_off = [&](int s) -> uint32_t { return sbase + s * 2 * STAGE_BYTES + STAGE_BYTES; };

    auto issue_stage = [&](int kt, int s) {
        const int k0 = kt * BK;
#pragma unroll
        for (int u = 0; u < 4; u++) {
            int idx = tid + u * 256;
            int row = idx >> 3;
            int c   = idx & 7;
            uint32_t sa = a_off(s) + row * ROWB + c * 16;
            const void* ga = A + (size_t)(m0 + row) * GK + k0 + c * 8;
            cp16(sa, ga, 16);
        }
#pragma unroll
        for (int u = 0; u < 4; u++) {
            int idx = tid + u * 256;
            int row = idx >> 3;
            int c   = idx & 7;
            uint32_t sa = b_off(s) + row * ROWB + c * 16;
            int gr = n0 + row;
            const void* ga = B + (size_t)(gr < N ? gr : N - 1) * GK + k0 + c * 8;
            cp16(sa, ga, (gr < N) ? 16u : 0u);
        }
        cp_commit();
    };

    float acc[4][4][4];
#pragma unroll
    for (int i = 0; i < 4; i++)
#pragma unroll
        for (int j = 0; j < 4; j++)
#pragma unroll
            for (int e = 0; e < 4; e++) acc[i][j][e] = 0.f;

    issue_stage(0, 0);
    issue_stage(1, 1);

    const int g    = lane >> 3;     // 0..3
    const int lrow = lane & 7;      // 0..7

    for (int kt = 0; kt < NKT; kt++) {
        const int s = kt % NSTAGE;
        if (kt + 2 < NKT) {
            issue_stage(kt + 2, (kt + 2) % NSTAGE);
            cp_wait<2>();
        } else if (kt + 1 < NKT) {
            cp_wait<1>();
        } else {
            cp_wait<0>();
        }
        __syncthreads();

        const uint32_t abase = a_off(s);
        const uint32_t bbase = b_off(s);

#pragma unroll
        for (int ks = 0; ks < 4; ks++) {
            uint32_t a[4][4];
#pragma unroll
            for (int mt = 0; mt < 4; mt++) {
                int row = warp_m * 64 + mt * 16 + lrow + (g & 1) * 8;
                int chunk = ks * 2 + (g >> 1);
                ldmx4(abase + row * ROWB + chunk * 16,
                      a[mt][0], a[mt][1], a[mt][2], a[mt][3]);
            }
            uint32_t b[4][2];
#pragma unroll
            for (int nt = 0; nt < 2; nt++) {
                int row = warp_n * 32 + nt * 16 + lrow + (g >> 1) * 8;
                int chunk = ks * 2 + (g & 1);
                uint32_t r0, r1, r2, r3;
                ldmx4(bbase + row * ROWB + chunk * 16, r0, r1, r2, r3);
                b[nt * 2 + 0][0] = r0; b[nt * 2 + 0][1] = r1;
                b[nt * 2 + 1][0] = r2; b[nt * 2 + 1][1] = r3;
            }
#pragma unroll
            for (int mt = 0; mt < 4; mt++)
#pragma unroll
                for (int nt = 0; nt < 4; nt++)
                    mma16816(acc[mt][nt][0], acc[mt][nt][1],
                             acc[mt][nt][2], acc[mt][nt][3],
                             a[mt][0], a[mt][1], a[mt][2], a[mt][3],
                             b[nt][0], b[nt][1]);
        }
        __syncthreads();
    }

    // ---- epilogue ----
    const int trow = lane >> 2;         // 0..7
    const int tcol = (lane & 3) * 2;    // 0,2,4,6
#pragma unroll
    for (int mt = 0; mt < 4; mt++) {
#pragma unroll
        for (int nt = 0; nt < 4; nt++) {
            int gm = m0 + warp_m * 64 + mt * 16 + trow;
            int gn = n0 + warp_n * 32 + nt * 8 + tcol;
            if (OUT_BF16) {
                // full tiles (N multiple of 128): no bounds check needed
                float2 bv = *reinterpret_cast<const float2*>(bias + gn);
                __nv_bfloat162 v0 = __floats2bfloat162_rn(
                    tanhf(acc[mt][nt][0] + bv.x), tanhf(acc[mt][nt][1] + bv.y));
                __nv_bfloat162 v1 = __floats2bfloat162_rn(
                    tanhf(acc[mt][nt][2] + bv.x), tanhf(acc[mt][nt][3] + bv.y));
                *reinterpret_cast<__nv_bfloat162*>(Cb + (size_t)gm * ldc + gn) = v0;
                *reinterpret_cast<__nv_bfloat162*>(Cb + (size_t)(gm + 8) * ldc + gn) = v1;
            } else {
                if (gn + 1 < N) {
                    float2 bv = *reinterpret_cast<const float2*>(bias + gn);
                    float2 v0 = make_float2(acc[mt][nt][0] + bv.x, acc[mt][nt][1] + bv.y);
                    float2 v1 = make_float2(acc[mt][nt][2] + bv.x, acc[mt][nt][3] + bv.y);
                    *reinterpret_cast<float2*>(Cf + (size_t)gm * ldc + gn) = v0;
                    *reinterpret_cast<float2*>(Cf + (size_t)(gm + 8) * ldc + gn) = v1;
                } else if (gn < N) {
                    float bb = bias[gn];
                    Cf[(size_t)gm * ldc + gn] = acc[mt][nt][0] + bb;
                    Cf[(size_t)(gm + 8) * ldc + gn] = acc[mt][nt][2] + bb;
                }
            }
        }
    }
}

// ===========================================================================
// fp32 -> bf16 conversion (vectorized)
// ===========================================================================
__global__ __launch_bounds__(256) void f32_to_bf16_kernel(
    const float4* __restrict__ in, uint2* __restrict__ out, int n4)
{
    int i = blockIdx.x * blockDim.x + threadIdx.x;
    if (i < n4) {
        float4 v = in[i];
        __nv_bfloat162 lo = __floats2bfloat162_rn(v.x, v.y);
        __nv_bfloat162 hi = __floats2bfloat162_rn(v.z, v.w);
        uint2 o;
        o.x = *reinterpret_cast<uint32_t*>(&lo);
        o.y = *reinterpret_cast<uint32_t*>(&hi);
        out[i] = o;
    }
}

// ===========================================================================
// gates: per row r, softmax over 3 of h . W_div[j] + b_div[j]; h is bf16.
// One warp per row, each lane covers 16 contiguous k.
// ===========================================================================
__global__ __launch_bounds__(256) void gates_kernel(
    const __nv_bfloat16* __restrict__ h,
    const float* __restrict__ Wdiv, const float* __restrict__ bdiv)
{
    const int warp = (blockIdx.x * blockDim.x + threadIdx.x) >> 5;
    const int lane = threadIdx.x & 31;
    if (warp >= M_ROWS) return;

    const int k0 = lane * 16;
    const uint4* hp = reinterpret_cast<const uint4*>(h + (size_t)warp * C_DIM + k0);
    uint4 p0 = hp[0];
    uint4 p1 = hp[1];
    float hv[16];
    {
        const uint32_t* w = &p0.x;
#pragma unroll
        for (int i = 0; i < 4; i++) {
            __nv_bfloat162 t = *reinterpret_cast<const __nv_bfloat162*>(&w[i]);
            float2 f = __bfloat1622float2(t);
            hv[i * 2] = f.x; hv[i * 2 + 1] = f.y;
        }
        const uint32_t* w1 = &p1.x;
#pragma unroll
        for (int i = 0; i < 4; i++) {
            __nv_bfloat162 t = *reinterpret_cast<const __nv_bfloat162*>(&w1[i]);
            float2 f = __bfloat1622float2(t);
            hv[8 + i * 2] = f.x; hv[8 + i * 2 + 1] = f.y;
        }
    }
    float s[3];
#pragma unroll
    for (int j = 0; j < 3; j++) {
        const float4* wp = reinterpret_cast<const float4*>(Wdiv + j * C_DIM + k0);
        float acc = 0.f;
#pragma unroll
        for (int q = 0; q < 4; q++) {
            float4 wv = wp[q];
            acc = fmaf(hv[q * 4 + 0], wv.x, acc);
            acc = fmaf(hv[q * 4 + 1], wv.y, acc);
            acc = fmaf(hv[q * 4 + 2], wv.z, acc);
            acc = fmaf(hv[q * 4 + 3], wv.w, acc);
        }
        s[j] = acc;
    }
#pragma unroll
    for (int o = 16; o > 0; o >>= 1) {
        s[0] += __shfl_xor_sync(0xffffffffu, s[0], o);
        s[1] += __shfl_xor_sync(0xffffffffu, s[1], o);
        s[2] += __shfl_xor_sync(0xffffffffu, s[2], o);
    }
    if (lane == 0) {
        float s0 = s[0] + bdiv[0], s1 = s[1] + bdiv[1], s2 = s[2] + bdiv[2];
        float mx = fmaxf(s0, fmaxf(s1, s2));
        float e0 = expf(s0 - mx), e1 = expf(s1 - mx), e2 = expf(s2 - mx);
        float inv = 1.f / (e0 + e1 + e2);
        g_gates[warp * 3 + 0] = e0 * inv;  // gen
        g_gates[warp * 3 + 1] = e2 * inv;  // copy (gates[...,2])
        g_gates[warp * 3 + 2] = e1 * inv;  // map  (gates[...,1])
    }
}

// ===========================================================================
// softmax + scatter + log (float4-vectorized)
// ===========================================================================
#define V4   (V_DIM / 4)      // 3000
#define T4   (TOT_DIM / 4)    // 3125

__global__ __launch_bounds__(512) void softmax_scatter_log_kernel(
    float* __restrict__ out,
    const float* __restrict__ align,        // (SRC, B, SNT)
    const int*   __restrict__ copy_seq)     // (SNT, B, 2)
{
    extern __shared__ __align__(16) float buf[];   // TOT_DIM floats
    __shared__ float red[17];

    const int r = blockIdx.x;
    const int s = r / BSZ;
    const int b = r % BSZ;
    const int tid = threadIdx.x;
    float* row = out + (size_t)r * TOT_DIM;
    float4* row4 = reinterpret_cast<float4*>(row);
    float4* buf4 = reinterpret_cast<float4*>(buf);

    // pass 1: load logits (float4), find max; zero ext region
    float lmax = -3.0e38f;
    for (int c = tid; c < V4; c += 512) {
        float4 v = row4[c];
        buf4[c] = v;
        lmax = fmaxf(fmaxf(fmaxf(lmax, v.x), fmaxf(v.y, v.z)), v.w);
    }
    for (int c = V4 + tid; c < T4; c += 512)
        buf4[c] = make_float4(0.f, 0.f, 0.f, 0.f);
#pragma unroll
    for (int o = 16; o > 0; o >>= 1)
        lmax = fmaxf(lmax, __shfl_xor_sync(0xffffffffu, lmax, o));
    if ((tid & 31) == 0) red[tid >> 5] = lmax;
    __syncthreads();
    if (tid < 32) {
        float v = (tid < 16) ? red[tid] : -3.0e38f;
#pragma unroll
        for (int o = 8; o > 0; o >>= 1)
            v = fmaxf(v, __shfl_xor_sync(0xffffffffu, v, o));
        if (tid == 0) red[16] = v;
    }
    __syncthreads();
    const float mx = red[16];

    // pass 2: exp + sum
    float lsum = 0.f;
    for (int c = tid; c < V4; c += 512) {
        float4 v = buf4[c];
        v.x = expf(v.x - mx); v.y = expf(v.y - mx);
        v.z = expf(v.z - mx); v.w = expf(v.w - mx);
        buf4[c] = v;
        lsum += (v.x + v.y) + (v.z + v.w);
    }
    __syncthreads();   // protect red[] reuse
#pragma unroll
    for (int o = 16; o > 0; o >>= 1)
        lsum += __shfl_xor_sync(0xffffffffu, lsum, o);
    if ((tid & 31) == 0) red[tid >> 5] = lsum;
    __syncthreads();
    if (tid < 32) {
        float v = (tid < 16) ? red[tid] : 0.f;
#pragma unroll
        for (int o = 8; o > 0; o >>= 1)
            v += __shfl_xor_sync(0xffffffffu, v, o);
        if (tid == 0) red[16] = v;
    }
    __syncthreads();
    const float sum = red[16];

    const float gen = g_gates[r * 3 + 0];
    const float cpy = g_gates[r * 3 + 1];
    const float mp  = g_gates[r * 3 + 2];
    const float scale = gen / sum;

    for (int c = tid; c < V4; c += 512) {
        float4 v = buf4[c];
        v.x *= scale; v.y *= scale; v.z *= scale; v.w *= scale;
        buf4[c] = v;
    }
    __syncthreads();

    // scatter-add 1024 copy probabilities
    const float* arow = align + ((size_t)s * BSZ + b) * SNT_LEN;
    for (int j = tid; j < 2 * SNT_LEN; j += 512) {
        int snt = j >> 1;
        int k = j & 1;
        int idx = copy_seq[((size_t)snt * BSZ + b) * 2 + k];
        float v = (k == 0 ? cpy : mp) * arow[snt];
        if (idx >= 0 && idx < TOT_DIM) atomicAdd(&buf[idx], v);
    }
    __syncthreads();

    // write log(p + 1e-12), float4
    for (int c = tid; c < T4; c += 512) {
        float4 v = buf4[c];
        v.x = logf(v.x + 1e-12f);
        v.y = logf(v.y + 1e-12f);
        v.z = logf(v.z + 1e-12f);
        v.w = logf(v.w + 1e-12f);
        row4[c] = v;
    }
}

// ===========================================================================
// arc_ll = log(arc + 1e-12)
// ===========================================================================
__global__ __launch_bounds__(256) void arc_log_kernel(
    const float4* __restrict__ in, float4* __restrict__ out, int n4)
{
    int i = blockIdx.x * blockDim.x + threadIdx.x;
    if (i < n4) {
        float4 v = in[i];
        v.x = logf(v.x + 1e-12f);
        v.y = logf(v.y + 1e-12f);
        v.z = logf(v.z + 1e-12f);
        v.w = logf(v.w + 1e-12f);
        out[i] = v;
    }
}

// ===========================================================================
extern "C" void kernel_launch(void* const* d_in, const int* in_sizes, int n_in,
                              void* d_out, int out_size)
{
    const float* align    = (const float*)d_in[0];
    const float* arc      = (const float*)d_in[1];
    const float* concept  = (const float*)d_in[3];
    const int*   copy_seq = (const int*)  d_in[4];
    const float* Wt       = (const float*)d_in[9];
    const float* bt       = (const float*)d_in[10];
    const float* Wg       = (const float*)d_in[11];
    const float* bg       = (const float*)d_in[12];
    const float* Wd       = (const float*)d_in[13];
    const float* bd       = (const float*)d_in[14];

    float* out = (float*)d_out;
    float* ll = out;                         // (SRC,B,TOT)
    float* arc_ll = out + LL_ELEMS;          // (SRC,B,SRC)

    __nv_bfloat16 *cbf = nullptr, *wtbf = nullptr, *hbf = nullptr, *wgbf = nullptr;
    cudaGetSymbolAddress((void**)&cbf,  g_concept_bf);
    cudaGetSymbolAddress((void**)&wtbf, g_Wt_bf);
    cudaGetSymbolAddress((void**)&hbf,  g_h_bf);
    cudaGetSymbolAddress((void**)&wgbf, g_Wg_bf);

    cudaFuncSetAttribute(gemm_mma_kernel<0>,
                         cudaFuncAttributeMaxDynamicSharedMemorySize, GEMM_SMEM);
    cudaFuncSetAttribute(gemm_mma_kernel<1>,
                         cudaFuncAttributeMaxDynamicSharedMemorySize, GEMM_SMEM);

    // 0) conversions to bf16
    {
        int n4 = M_ROWS * E_DIM / 4;
        f32_to_bf16_kernel<<<(n4 + 255) / 256, 256>>>(
            (const float4*)concept, (uint2*)cbf, n4);
        int n4t = C_DIM * E_DIM / 4;
        f32_to_bf16_kernel<<<(n4t + 255) / 256, 256>>>(
            (const float4*)Wt, (uint2*)wtbf, n4t);
        int n4w = V_DIM * C_DIM / 4;
        f32_to_bf16_kernel<<<(n4w + 255) / 256, 256>>>(
            (const float4*)Wg, (uint2*)wgbf, n4w);
    }

    // 1) h = tanh(concept @ Wt^T + bt) -> bf16  [8192 x 512]
    {
        dim3 grid(C_DIM / 128, M_ROWS / 128);
        gemm_mma_kernel<1><<<grid, 256, GEMM_SMEM>>>(
            cbf, wtbf, bt, nullptr, hbf, C_DIM, C_DIM);
    }

    // 2) gates (bf16 h)
    gates_kernel<<<(M_ROWS * 32) / 256, 256>>>(hbf, Wd, bd);

    // 3) logits = h @ Wg^T + bg -> fp32 staged into ll region
    {
        dim3 grid((V_DIM + 127) / 128, M_ROWS / 128);
        gemm_mma_kernel<0><<<grid, 256, GEMM_SMEM>>>(
            hbf, wgbf, bg, ll, nullptr, V_DIM, TOT_DIM);
    }

    // 4) softmax * gen, zero-extend, scatter copy probs, log
    {
        int smem = TOT_DIM * sizeof(float);  // 50000 B
        cudaFuncSetAttribute(softmax_scatter_log_kernel,
                             cudaFuncAttributeMaxDynamicSharedMemorySize, smem);
        softmax_scatter_log_kernel<<<M_ROWS, 512, smem>>>(ll, align, copy_seq);
    }

    // 5) arc_ll
    {
        int n4 = (SRC_LEN * BSZ * SRC_LEN) / 4;
        arc_log_kernel<<<(n4 + 255) / 256, 256>>>((const float4*)arc,
                                                  (float4*)arc_ll, n4);
    }
}